// round 16
// baseline (speedup 1.0000x reference)
#include <cuda_runtime.h>
#include <cuda_fp16.h>
#include <cstdint>
#include <cstddef>

#define BB  32
#define CC  1024
#define HWN 1024
#define CH  512
#define HB  16                      // half-batch

// ============================================================================
// Scratch (device globals; no cudaMalloc allowed)
// ============================================================================
__device__ __half g_xt_h[(size_t)BB * HWN * CC];   // x^T  [b][n][c] hi
__device__ __half g_xt_l[(size_t)BB * HWN * CC];   //               lo
__device__ __half g_wqk_h[1024 * CC], g_wqk_l[1024 * CC]; // stacked [Wq;Wk]
__device__ float  g_bqk[1024];
__device__ __half g_wv_h[CC * CC];
__device__ __half g_qk_h[(size_t)BB * HWN * 1024];  // cols 0..511 = q, 512..1023 = k
__device__ __half g_qk_l[(size_t)BB * HWN * 1024];
__device__ __half g_v_h[(size_t)BB * HWN * CC];
__device__ float  g_logits[(size_t)BB * HWN * HWN];
__device__ __half g_a_h[(size_t)BB * HWN * HWN];

// ============================================================================
// PTX helpers (plain sm_103-legal: cp.async, ldmatrix, mma.sync)
// ============================================================================
__device__ __forceinline__ uint32_t smem_u32(const void* p) {
    uint32_t a;
    asm("{ .reg .u64 t; cvta.to.shared.u64 t, %1; cvt.u32.u64 %0, t; }"
        : "=r"(a) : "l"(p));
    return a;
}
__device__ __forceinline__ void cp_async16(uint32_t dst, const void* src) {
    asm volatile("cp.async.cg.shared.global [%0], [%1], 16;"
                 :: "r"(dst), "l"(src) : "memory");
}
__device__ __forceinline__ void cp_commit() {
    asm volatile("cp.async.commit_group;" ::: "memory");
}
template <int N>
__device__ __forceinline__ void cp_wait() {
    asm volatile("cp.async.wait_group %0;" :: "n"(N) : "memory");
}
__device__ __forceinline__ void ldsm_x4(uint32_t* r, uint32_t addr) {
    asm volatile("ldmatrix.sync.aligned.m8n8.x4.shared.b16 {%0,%1,%2,%3}, [%4];"
                 : "=r"(r[0]), "=r"(r[1]), "=r"(r[2]), "=r"(r[3]) : "r"(addr));
}
__device__ __forceinline__ void mma16816(float* c, const uint32_t* a, const uint32_t* b) {
    asm volatile(
        "mma.sync.aligned.m16n8k16.row.col.f32.f16.f16.f32 "
        "{%0,%1,%2,%3}, {%4,%5,%6,%7}, {%8,%9}, {%0,%1,%2,%3};"
        : "+f"(c[0]), "+f"(c[1]), "+f"(c[2]), "+f"(c[3])
        : "r"(a[0]), "r"(a[1]), "r"(a[2]), "r"(a[3]), "r"(b[0]), "r"(b[1]));
}
__device__ __forceinline__ void split_f32(float v, __half& h, __half& l) {
    h = __float2half(v);
    l = __float2half(v - __half2float(h));
}

// ============================================================================
// conversions / packing
// ============================================================================
__global__ void __launch_bounds__(1024)
transpose_split_x(const float* __restrict__ x,
                  __half* __restrict__ xh, __half* __restrict__ xl)
{
    __shared__ float t[32][33];
    int b = blockIdx.z, c0 = blockIdx.y * 32, n0 = blockIdx.x * 32;
    int tx = threadIdx.x, ty = threadIdx.y;
    t[ty][tx] = x[((size_t)b * CC + c0 + ty) * HWN + n0 + tx];
    __syncthreads();
    float v = t[tx][ty];
    size_t off = ((size_t)b * HWN + n0 + ty) * CC + c0 + tx;
    __half h, l; split_f32(v, h, l);
    xh[off] = h; xl[off] = l;
}

// single conversion kernel: stacked [Wq;Wk] split + Wv tohalf + stacked bias
__global__ void __launch_bounds__(256)
pack_weights(const float* __restrict__ Wq, const float* __restrict__ Wk,
             const float* __restrict__ Wv,
             const float* __restrict__ bq, const float* __restrict__ bk,
             __half* __restrict__ wh, __half* __restrict__ wl,
             __half* __restrict__ wvh, float* __restrict__ bqk)
{
    int i = blockIdx.x * 256 + threadIdx.x;     // 0 .. 1024*1024-1
    int o = i >> 10, c = i & 1023;
    float v = (o < CH) ? Wq[o * CC + c] : Wk[(o - CH) * CC + c];
    __half h, l; split_f32(v, h, l);
    wh[i] = h; wl[i] = l;
    wvh[i] = __float2half(Wv[i]);
    if (i < 1024) bqk[i] = (i < CH) ? bq[i] : bk[i - CH];
}

// ============================================================================
// NT GEMM on mma.sync (HMMA), TERMS = 3 (split-fp16 emulated fp32) or 1 (fp16)
//   C[b][m][n] = sum_k A[b][m][k] * B[b][n][k]
// CTA tile 128x128, 128 threads = 4 warps, warp tile 64x64.
// 3-stage cp.async pipeline, 2 CTAs/SM.
// Pipeline order wait -> syncthreads -> issue-loads is REQUIRED: cp.async
// wait_group is per-thread; the barrier AFTER the wait makes all threads'
// stage writes visible before any ldsm.
// ============================================================================
#define BM 128
#define BN 128
#define STAGES 3
#define STAGE_BYTES 32768
#define SMEM_TOTAL (STAGES * STAGE_BYTES)

template <int K, int TERMS, int MODE>
__global__ void __launch_bounds__(128, 2)
mma_gemm(const __half* __restrict__ Ah, const __half* __restrict__ Al,
         const __half* __restrict__ Bh, const __half* __restrict__ Bl,
         int lda, int ldb, size_t strideA, size_t strideB,
         const float* __restrict__ bias, const float* __restrict__ xadd,
         float* __restrict__ Cf, __half* __restrict__ Ch, __half* __restrict__ Cl,
         int Nfull)
{
    extern __shared__ char dsm[];
    const uint32_t base = smem_u32(dsm);

    constexpr int BKv    = (TERMS == 3) ? 32 : 64;
    constexpr int KSTEPS = (TERMS == 3) ? 2 : 4;
    constexpr int NK     = K / BKv;

    const int tid  = threadIdx.x;
    const int wid  = tid >> 5;
    const int lane = tid & 31;
    const int b    = blockIdx.z;
    const int m0   = blockIdx.y * BM;
    const int n0   = blockIdx.x * BN;
    const int wm   = (wid >> 1) * 64;   // 2x2 warp grid, 64x64 per warp
    const int wn   = (wid & 1) * 64;

    const __half* Abh = Ah + (size_t)b * strideA;
    const __half* Abl = (TERMS == 3) ? (Al + (size_t)b * strideA) : nullptr;
    const __half* Bbh = Bh + (size_t)b * strideB;
    const __half* Bbl = (TERMS == 3) ? (Bl + (size_t)b * strideB) : nullptr;

    // ---- async stage loader: 2048 x 16B per stage, 128 threads ----
    auto load_stage = [&](int ci, int st) {
        const int kk = ci * BKv;
#pragma unroll
        for (int it = 0; it < 16; ++it) {
            int idx = it * 128 + tid;
            int isB = idx >> 10;
            int row = (idx >> 3) & 127;
            int ch  = idx & 7;
            const __half* src;
            if (TERMS == 3) {
                if (!isB) src = ((ch < 4) ? Abh : Abl) + (size_t)(m0 + row) * lda + kk + (ch & 3) * 8;
                else      src = ((ch < 4) ? Bbh : Bbl) + (size_t)(n0 + row) * ldb + kk + (ch & 3) * 8;
            } else {
                if (!isB) src = Abh + (size_t)(m0 + row) * lda + kk + ch * 8;
                else      src = Bbh + (size_t)(n0 + row) * ldb + kk + ch * 8;
            }
            uint32_t dst = base + st * STAGE_BYTES + isB * 16384
                         + row * 128 + ((ch ^ (row & 7)) << 4);
            cp_async16(dst, src);
        }
        cp_commit();
    };

    float acc[4][8][4];
#pragma unroll
    for (int i = 0; i < 4; ++i)
#pragma unroll
        for (int j = 0; j < 8; ++j)
#pragma unroll
            for (int r = 0; r < 4; ++r) acc[i][j][r] = 0.f;

#pragma unroll
    for (int s = 0; s < STAGES - 1; ++s) load_stage(s, s);

    const int rA   = wm + (lane & 15);
    const int selA = (lane >> 4);
    const int rB   = wn + ((lane >> 4) << 3) + (lane & 7);
    const int selB = (lane >> 3) & 1;

    for (int ks = 0; ks < NK; ++ks) {
        cp_wait<STAGES - 2>();   // own chunk-ks copies done
        __syncthreads();         // -> ALL threads' copies visible
        if (ks + STAGES - 1 < NK) load_stage(ks + STAGES - 1, (ks + STAGES - 1) % STAGES);
        else cp_commit();        // keep wait_group positional depth on tails

        const uint32_t sA = base + (ks % STAGES) * STAGE_BYTES;
        const uint32_t sB = sA + 16384;

        if (TERMS == 3) {
#pragma unroll
            for (int kstep = 0; kstep < KSTEPS; ++kstep) {
                const int cA = kstep * 2 + selA;
                const int cB = kstep * 2 + selB;
                uint32_t ah[4][4], bh[4][4];
#pragma unroll
                for (int mt = 0; mt < 4; ++mt) {
                    int r = rA + mt * 16;
                    ldsm_x4(ah[mt], sA + r * 128 + ((cA ^ (r & 7)) << 4));
                }
#pragma unroll
                for (int ntp = 0; ntp < 4; ++ntp) {
                    int r = rB + ntp * 16;
                    ldsm_x4(bh[ntp], sB + r * 128 + ((cB ^ (r & 7)) << 4));
                }
                // term 1: ah * bh
#pragma unroll
                for (int mt = 0; mt < 4; ++mt)
#pragma unroll
                    for (int nt = 0; nt < 8; ++nt)
                        mma16816(acc[mt][nt], ah[mt], &bh[nt >> 1][(nt & 1) * 2]);
                // term 3: al * bh  — al loaded in 2-fragment halves
                {
                    uint32_t al[2][4];
#pragma unroll
                    for (int half = 0; half < 2; ++half) {
#pragma unroll
                        for (int m2 = 0; m2 < 2; ++m2) {
                            int mt = half * 2 + m2;
                            int r = rA + mt * 16;
                            ldsm_x4(al[m2], sA + r * 128 + (((cA + 4) ^ (r & 7)) << 4));
                        }
#pragma unroll
                        for (int m2 = 0; m2 < 2; ++m2)
#pragma unroll
                            for (int nt = 0; nt < 8; ++nt)
                                mma16816(acc[half * 2 + m2][nt], al[m2],
                                         &bh[nt >> 1][(nt & 1) * 2]);
                    }
                }
                // term 2: ah * bl  — bl loaded in 2-fragment halves
                {
                    uint32_t bl[2][4];
#pragma unroll
                    for (int half = 0; half < 2; ++half) {
#pragma unroll
                        for (int n2 = 0; n2 < 2; ++n2) {
                            int ntp = half * 2 + n2;
                            int r = rB + ntp * 16;
                            ldsm_x4(bl[n2], sB + r * 128 + (((cB + 4) ^ (r & 7)) << 4));
                        }
#pragma unroll
                        for (int mt = 0; mt < 4; ++mt)
#pragma unroll
                            for (int nt = 0; nt < 4; ++nt)
                                mma16816(acc[mt][half * 4 + nt], ah[mt],
                                         &bl[nt >> 1][(nt & 1) * 2]);
                    }
                }
            }
        } else {
            // 1-term: fragment double-buffering across ksteps
            uint32_t ah[2][4][4], bh[2][4][4];
            auto load_frags = [&](int kstep, int buf) {
                const int cA = kstep * 2 + selA;
                const int cB = kstep * 2 + selB;
#pragma unroll
                for (int mt = 0; mt < 4; ++mt) {
                    int r = rA + mt * 16;
                    ldsm_x4(ah[buf][mt], sA + r * 128 + ((cA ^ (r & 7)) << 4));
                }
#pragma unroll
                for (int ntp = 0; ntp < 4; ++ntp) {
                    int r = rB + ntp * 16;
                    ldsm_x4(bh[buf][ntp], sB + r * 128 + ((cB ^ (r & 7)) << 4));
                }
            };
            load_frags(0, 0);
#pragma unroll
            for (int kstep = 0; kstep < KSTEPS; ++kstep) {
                if (kstep + 1 < KSTEPS) load_frags(kstep + 1, (kstep + 1) & 1);
                const int buf = kstep & 1;
#pragma unroll
                for (int mt = 0; mt < 4; ++mt)
#pragma unroll
                    for (int nt = 0; nt < 8; ++nt)
                        mma16816(acc[mt][nt], ah[buf][mt], &bh[buf][nt >> 1][(nt & 1) * 2]);
            }
        }
    }

    // ---- epilogue ----
    const int erow = lane >> 2;
    const int ecol = (lane & 3) * 2;

    float bv[8][2];
    if (MODE == 0 || MODE == 3) {
#pragma unroll
        for (int nt = 0; nt < 8; ++nt) {
            bv[nt][0] = bias[n0 + wn + nt * 8 + ecol];
            bv[nt][1] = bias[n0 + wn + nt * 8 + ecol + 1];
        }
    }

#pragma unroll
    for (int mt = 0; mt < 4; ++mt) {
#pragma unroll
        for (int nt = 0; nt < 8; ++nt) {
            int m1 = m0 + wm + mt * 16 + erow;
            int nn = n0 + wn + nt * 8 + ecol;
            size_t off1 = ((size_t)b * HWN + m1) * (size_t)Nfull + nn;
            size_t off2 = off1 + 8 * (size_t)Nfull;
            if (MODE == 0) {
                float y0 = acc[mt][nt][0] + bv[nt][0];
                float y1 = acc[mt][nt][1] + bv[nt][1];
                float y2 = acc[mt][nt][2] + bv[nt][0];
                float y3 = acc[mt][nt][3] + bv[nt][1];
                __half h0, l0, h1, l1, h2, l2, h3, l3;
                split_f32(y0, h0, l0); split_f32(y1, h1, l1);
                split_f32(y2, h2, l2); split_f32(y3, h3, l3);
                *(__half2*)(Ch + off1) = __halves2half2(h0, h1);
                *(__half2*)(Cl + off1) = __halves2half2(l0, l1);
                *(__half2*)(Ch + off2) = __halves2half2(h2, h3);
                *(__half2*)(Cl + off2) = __halves2half2(l2, l3);
            } else if (MODE == 3) {
                float y0 = acc[mt][nt][0] + bv[nt][0];
                float y1 = acc[mt][nt][1] + bv[nt][1];
                float y2 = acc[mt][nt][2] + bv[nt][0];
                float y3 = acc[mt][nt][3] + bv[nt][1];
                *(__half2*)(Ch + off1) = __halves2half2(__float2half(y0), __float2half(y1));
                *(__half2*)(Ch + off2) = __halves2half2(__float2half(y2), __float2half(y3));
            } else {
                float2 r1 = make_float2(acc[mt][nt][0], acc[mt][nt][1]);
                float2 r2 = make_float2(acc[mt][nt][2], acc[mt][nt][3]);
                if (MODE == 2) {
                    float2 x1 = *(const float2*)(xadd + off1);
                    float2 x2 = *(const float2*)(xadd + off2);
                    r1.x += x1.x; r1.y += x1.y;
                    r2.x += x2.x; r2.y += x2.y;
                }
                *(float2*)(Cf + off1) = r1;
                *(float2*)(Cf + off2) = r2;
            }
        }
    }
}

// ============================================================================
// softmax: one WARP per row (1024 cols = 8 float4 per lane), shfl-only
// ============================================================================
__global__ void __launch_bounds__(256)
softmax_h(const float* __restrict__ logits, __half2* __restrict__ ah)
{
    const int lane = threadIdx.x & 31;
    const int w    = threadIdx.x >> 5;
    const size_t row = (size_t)blockIdx.x * 8 + w;

    const float4* src = (const float4*)(logits + row * HWN);
    float4 v[8];
#pragma unroll
    for (int i = 0; i < 8; ++i) v[i] = src[lane + 32 * i];

    float m = -3.4e38f;
#pragma unroll
    for (int i = 0; i < 8; ++i)
        m = fmaxf(m, fmaxf(fmaxf(v[i].x, v[i].y), fmaxf(v[i].z, v[i].w)));
#pragma unroll
    for (int o = 16; o; o >>= 1) m = fmaxf(m, __shfl_xor_sync(0xffffffffu, m, o));

    float s = 0.f;
#pragma unroll
    for (int i = 0; i < 8; ++i) {
        v[i].x = __expf(v[i].x - m); v[i].y = __expf(v[i].y - m);
        v[i].z = __expf(v[i].z - m); v[i].w = __expf(v[i].w - m);
        s += (v[i].x + v[i].y) + (v[i].z + v[i].w);
    }
#pragma unroll
    for (int o = 16; o; o >>= 1) s += __shfl_xor_sync(0xffffffffu, s, o);

    const float inv = 1.f / s;
    __half2* dst = ah + row * (HWN / 2);
#pragma unroll
    for (int i = 0; i < 8; ++i) {
        int c4 = lane + 32 * i;
        dst[c4 * 2]     = __halves2half2(__float2half(v[i].x * inv),
                                         __float2half(v[i].y * inv));
        dst[c4 * 2 + 1] = __halves2half2(__float2half(v[i].z * inv),
                                         __float2half(v[i].w * inv));
    }
}

// ============================================================================
// Launch — 2-way batch pipeline (halves h1 = [0,16), h2 = [16,32))
// ============================================================================
extern "C" void kernel_launch(void* const* d_in, const int* in_sizes, int n_in,
                              void* d_out, int out_size)
{
    (void)in_sizes; (void)n_in; (void)out_size;
    const float* x  = (const float*)d_in[0];
    const float* Wq = (const float*)d_in[1];
    const float* bq = (const float*)d_in[2];
    const float* Wk = (const float*)d_in[3];
    const float* bk = (const float*)d_in[4];
    const float* Wv = (const float*)d_in[5];
    const float* bv = (const float*)d_in[6];
    float* out = (float*)d_out;

    __half *xth, *xtl, *wqkh, *wqkl, *wvh, *qkh, *qkl, *vh, *aah;
    float *lg, *bqk;
    cudaGetSymbolAddress((void**)&xth,  g_xt_h);
    cudaGetSymbolAddress((void**)&xtl,  g_xt_l);
    cudaGetSymbolAddress((void**)&wqkh, g_wqk_h);
    cudaGetSymbolAddress((void**)&wqkl, g_wqk_l);
    cudaGetSymbolAddress((void**)&bqk,  g_bqk);
    cudaGetSymbolAddress((void**)&wvh,  g_wv_h);
    cudaGetSymbolAddress((void**)&qkh,  g_qk_h);
    cudaGetSymbolAddress((void**)&qkl,  g_qk_l);
    cudaGetSymbolAddress((void**)&vh,   g_v_h);
    cudaGetSymbolAddress((void**)&lg,   g_logits);
    cudaGetSymbolAddress((void**)&aah,  g_a_h);

    cudaFuncSetAttribute(mma_gemm<1024, 3, 0>, cudaFuncAttributeMaxDynamicSharedMemorySize, SMEM_TOTAL);
    cudaFuncSetAttribute(mma_gemm<512,  3, 1>, cudaFuncAttributeMaxDynamicSharedMemorySize, SMEM_TOTAL);
    cudaFuncSetAttribute(mma_gemm<1024, 1, 3>, cudaFuncAttributeMaxDynamicSharedMemorySize, SMEM_TOTAL);
    cudaFuncSetAttribute(mma_gemm<1024, 1, 2>, cudaFuncAttributeMaxDynamicSharedMemorySize, SMEM_TOTAL);

    static cudaStream_t s2 = nullptr;
    static cudaEvent_t ev_f = nullptr, ev_x = nullptr, ev_w = nullptr;
    static cudaEvent_t ev_q1 = nullptr, ev_v = nullptr, ev_join = nullptr;
    if (s2 == nullptr) {
        cudaStreamCreateWithFlags(&s2, cudaStreamNonBlocking);
        cudaEventCreateWithFlags(&ev_f,    cudaEventDisableTiming);
        cudaEventCreateWithFlags(&ev_x,    cudaEventDisableTiming);
        cudaEventCreateWithFlags(&ev_w,    cudaEventDisableTiming);
        cudaEventCreateWithFlags(&ev_q1,   cudaEventDisableTiming);
        cudaEventCreateWithFlags(&ev_v,    cudaEventDisableTiming);
        cudaEventCreateWithFlags(&ev_join, cudaEventDisableTiming);
    }

    // element offsets for the second half-batch
    const size_t OXT = (size_t)HB * HWN * CC;      // xt halves
    const size_t OQK = (size_t)HB * HWN * 1024;    // qk halves
    const size_t OV  = (size_t)HB * HWN * CC;      // v halves
    const size_t OLG = (size_t)HB * HWN * HWN;     // logits floats
    const size_t OX  = (size_t)HB * CC * HWN;      // x / out floats

    // fork s2 from main
    cudaEventRecord(ev_f, 0);
    cudaStreamWaitEvent(s2, ev_f, 0);

    // conversions: transpose on main, weight pack on s2
    transpose_split_x<<<dim3(32, 32, 32), dim3(32, 32)>>>(x, xth, xtl);
    pack_weights<<<4096, 256, 0, s2>>>(Wq, Wk, Wv, bq, bk, wqkh, wqkl, wvh, bqk);
    cudaEventRecord(ev_w, s2);
    cudaEventRecord(ev_x, 0);
    cudaStreamWaitEvent(0, ev_w, 0);     // main needs weights
    cudaStreamWaitEvent(s2, ev_x, 0);    // s2 needs xt

    // ---- main: qk-proj h1 then h2 ----
    mma_gemm<1024, 3, 0><<<dim3(8, 8, HB), 128, SMEM_TOTAL>>>(
        xth, xtl, wqkh, wqkl, CC, CC, (size_t)HWN * CC, 0,
        bqk, nullptr, nullptr, qkh, qkl, 1024);
    cudaEventRecord(ev_q1, 0);
    mma_gemm<1024, 3, 0><<<dim3(8, 8, HB), 128, SMEM_TOTAL>>>(
        xth + OXT, xtl + OXT, wqkh, wqkl, CC, CC, (size_t)HWN * CC, 0,
        bqk, nullptr, nullptr, qkh + OQK, qkl + OQK, 1024);

    // ---- s2: v-proj (full batch), then h1 chain ----
    mma_gemm<1024, 1, 3><<<dim3(8, 8, BB), 128, SMEM_TOTAL, s2>>>(
        xth, nullptr, wvh, nullptr, CC, CC, (size_t)HWN * CC, 0,
        bv, nullptr, nullptr, vh, nullptr, CC);
    cudaEventRecord(ev_v, s2);
    cudaStreamWaitEvent(s2, ev_q1, 0);
    mma_gemm<512, 3, 1><<<dim3(8, 8, HB), 128, SMEM_TOTAL, s2>>>(
        qkh, qkl, qkh + CH, qkl + CH, 1024, 1024,
        (size_t)HWN * 1024, (size_t)HWN * 1024,
        nullptr, nullptr, lg, nullptr, nullptr, HWN);
    softmax_h<<<HB * HWN / 8, 256, 0, s2>>>(lg, (__half2*)aah);
    mma_gemm<1024, 1, 2><<<dim3(8, 8, HB), 128, SMEM_TOTAL, s2>>>(
        vh, nullptr, aah, nullptr, CC, HWN, (size_t)HWN * CC, (size_t)HWN * HWN,
        nullptr, x, out, nullptr, nullptr, HWN);
    cudaEventRecord(ev_join, s2);

    // ---- main: h2 chain ----
    mma_gemm<512, 3, 1><<<dim3(8, 8, HB), 128, SMEM_TOTAL>>>(
        qkh + OQK, qkl + OQK, qkh + OQK + CH, qkl + OQK + CH, 1024, 1024,
        (size_t)HWN * 1024, (size_t)HWN * 1024,
        nullptr, nullptr, lg + OLG, nullptr, nullptr, HWN);
    softmax_h<<<HB * HWN / 8, 256>>>(lg + OLG, (__half2*)(aah + OLG));
    cudaStreamWaitEvent(0, ev_v, 0);     // out h2 needs v
    mma_gemm<1024, 1, 2><<<dim3(8, 8, HB), 128, SMEM_TOTAL>>>(
        vh + OV, nullptr, aah + OLG, nullptr, CC, HWN,
        (size_t)HWN * CC, (size_t)HWN * HWN,
        nullptr, x + OX, out + OX, nullptr, nullptr, HWN);

    // join s2's h1 chain back to main
    cudaStreamWaitEvent(0, ev_join, 0);
}

// round 17
// speedup vs baseline: 1.0495x; 1.0495x over previous
#include <cuda_runtime.h>
#include <cuda_fp16.h>
#include <cstdint>
#include <cstddef>

#define BB  32
#define CC  1024
#define HWN 1024
#define CH  512

// ============================================================================
// Scratch (device globals; no cudaMalloc allowed)
// ============================================================================
__device__ __half g_xt_h[(size_t)BB * HWN * CC];   // x^T  [b][n][c] hi
__device__ __half g_xt_l[(size_t)BB * HWN * CC];   //               lo
__device__ __half g_wqk_h[1024 * CC], g_wqk_l[1024 * CC]; // stacked [Wq;Wk]
__device__ float  g_bqk[1024];
__device__ __half g_wv_h[CC * CC];
__device__ __half g_qk_h[(size_t)BB * HWN * 1024];  // cols 0..511 = q, 512..1023 = k
__device__ __half g_qk_l[(size_t)BB * HWN * 1024];
__device__ __half g_v_h[(size_t)BB * HWN * CC];
__device__ float  g_logits[(size_t)BB * HWN * HWN];
__device__ __half g_a_h[(size_t)BB * HWN * HWN];

// ============================================================================
// PTX helpers (plain sm_103-legal: cp.async, ldmatrix, mma.sync)
// ============================================================================
__device__ __forceinline__ uint32_t smem_u32(const void* p) {
    uint32_t a;
    asm("{ .reg .u64 t; cvta.to.shared.u64 t, %1; cvt.u32.u64 %0, t; }"
        : "=r"(a) : "l"(p));
    return a;
}
__device__ __forceinline__ void cp_async16(uint32_t dst, const void* src) {
    asm volatile("cp.async.cg.shared.global [%0], [%1], 16;"
                 :: "r"(dst), "l"(src) : "memory");
}
__device__ __forceinline__ void cp_commit() {
    asm volatile("cp.async.commit_group;" ::: "memory");
}
template <int N>
__device__ __forceinline__ void cp_wait() {
    asm volatile("cp.async.wait_group %0;" :: "n"(N) : "memory");
}
__device__ __forceinline__ void ldsm_x4(uint32_t* r, uint32_t addr) {
    asm volatile("ldmatrix.sync.aligned.m8n8.x4.shared.b16 {%0,%1,%2,%3}, [%4];"
                 : "=r"(r[0]), "=r"(r[1]), "=r"(r[2]), "=r"(r[3]) : "r"(addr));
}
__device__ __forceinline__ void mma16816(float* c, const uint32_t* a, const uint32_t* b) {
    asm volatile(
        "mma.sync.aligned.m16n8k16.row.col.f32.f16.f16.f32 "
        "{%0,%1,%2,%3}, {%4,%5,%6,%7}, {%8,%9}, {%0,%1,%2,%3};"
        : "+f"(c[0]), "+f"(c[1]), "+f"(c[2]), "+f"(c[3])
        : "r"(a[0]), "r"(a[1]), "r"(a[2]), "r"(a[3]), "r"(b[0]), "r"(b[1]));
}
__device__ __forceinline__ void split_f32(float v, __half& h, __half& l) {
    h = __float2half(v);
    l = __float2half(v - __half2float(h));
}

// ============================================================================
// conversions / packing
// ============================================================================
// 32x32 tile transpose; each thread handles 2 adjacent c-values so the
// global stores are 4-byte __half2 (halves the store count vs 2B stores).
__global__ void __launch_bounds__(512)
transpose_split_x(const float* __restrict__ x,
                  __half* __restrict__ xh, __half* __restrict__ xl)
{
    __shared__ float t[32][33];
    int b = blockIdx.z, c0 = blockIdx.y * 32, n0 = blockIdx.x * 32;
    int tx = threadIdx.x & 31;          // n within tile (load) / c pair base (store)
    int ty = threadIdx.x >> 5;          // 0..15
    // load 32x32 fp32 tile (each thread 2 rows)
    t[ty * 2][tx]     = x[((size_t)b * CC + c0 + ty * 2) * HWN + n0 + tx];
    t[ty * 2 + 1][tx] = x[((size_t)b * CC + c0 + ty * 2 + 1) * HWN + n0 + tx];
    __syncthreads();
    // store transposed: thread handles (n = ty*2..+1? no) — n = tx? remap:
    // write row n0+r (r = threadIdx.x>>4), cols c0 + 2*(threadIdx.x&15)
    int r  = threadIdx.x >> 4;          // 0..31  (n index)
    int cp = (threadIdx.x & 15) * 2;    // 0,2,..30 (c pair)
    float v0 = t[cp][r], v1 = t[cp + 1][r];
    __half h0, l0, h1, l1;
    split_f32(v0, h0, l0); split_f32(v1, h1, l1);
    size_t off = ((size_t)b * HWN + n0 + r) * CC + c0 + cp;
    *(__half2*)(xh + off) = __halves2half2(h0, h1);
    *(__half2*)(xl + off) = __halves2half2(l0, l1);
}

// single conversion kernel: stacked [Wq;Wk] split + Wv tohalf + stacked bias
__global__ void __launch_bounds__(256)
pack_weights(const float* __restrict__ Wq, const float* __restrict__ Wk,
             const float* __restrict__ Wv,
             const float* __restrict__ bq, const float* __restrict__ bk,
             __half* __restrict__ wh, __half* __restrict__ wl,
             __half* __restrict__ wvh, float* __restrict__ bqk)
{
    int i = blockIdx.x * 256 + threadIdx.x;     // 0 .. 1024*1024-1
    int o = i >> 10, c = i & 1023;
    float v = (o < CH) ? Wq[o * CC + c] : Wk[(o - CH) * CC + c];
    __half h, l; split_f32(v, h, l);
    wh[i] = h; wl[i] = l;
    wvh[i] = __float2half(Wv[i]);
    if (i < 1024) bqk[i] = (i < CH) ? bq[i] : bk[i - CH];
}

// ============================================================================
// NT GEMM on mma.sync (HMMA), TERMS = 3 (split-fp16 emulated fp32) or 1 (fp16)
//   C[b][m][n] = sum_k A[b][m][k] * B[b][n][k]
// CTA tile 128x128, 128 threads = 4 warps, warp tile 64x64.
// 3-stage cp.async pipeline, 2 CTAs/SM.
// Pipeline order wait -> syncthreads is REQUIRED (cp.async wait_group is
// per-thread; the barrier makes all threads' stage writes visible).
// After the barrier, the FIRST kstep's ldsm batch is issued BEFORE the next
// stage's cp.async block: ldsm reads stage ks%3 while cp.async writes stage
// (ks+2)%3 (disjoint), and this lets MMAs start ~128 cycles earlier per chunk
// instead of stalling behind 16 volatile cp.async issues.
// ============================================================================
#define BM 128
#define BN 128
#define STAGES 3
#define STAGE_BYTES 32768
#define SMEM_TOTAL (STAGES * STAGE_BYTES)

template <int K, int TERMS, int MODE>
__global__ void __launch_bounds__(128, 2)
mma_gemm(const __half* __restrict__ Ah, const __half* __restrict__ Al,
         const __half* __restrict__ Bh, const __half* __restrict__ Bl,
         int lda, int ldb, size_t strideA, size_t strideB,
         const float* __restrict__ bias, const float* __restrict__ xadd,
         float* __restrict__ Cf, __half* __restrict__ Ch, __half* __restrict__ Cl,
         int Nfull)
{
    extern __shared__ char dsm[];
    const uint32_t base = smem_u32(dsm);

    constexpr int BKv    = (TERMS == 3) ? 32 : 64;
    constexpr int KSTEPS = (TERMS == 3) ? 2 : 4;
    constexpr int NK     = K / BKv;

    const int tid  = threadIdx.x;
    const int wid  = tid >> 5;
    const int lane = tid & 31;
    const int b    = blockIdx.z;
    const int m0   = blockIdx.y * BM;
    const int n0   = blockIdx.x * BN;
    const int wm   = (wid >> 1) * 64;   // 2x2 warp grid, 64x64 per warp
    const int wn   = (wid & 1) * 64;

    const __half* Abh = Ah + (size_t)b * strideA;
    const __half* Abl = (TERMS == 3) ? (Al + (size_t)b * strideA) : nullptr;
    const __half* Bbh = Bh + (size_t)b * strideB;
    const __half* Bbl = (TERMS == 3) ? (Bl + (size_t)b * strideB) : nullptr;

    // ---- async stage loader: 2048 x 16B per stage, 128 threads ----
    auto load_stage = [&](int ci, int st) {
        const int kk = ci * BKv;
#pragma unroll
        for (int it = 0; it < 16; ++it) {
            int idx = it * 128 + tid;
            int isB = idx >> 10;
            int row = (idx >> 3) & 127;
            int ch  = idx & 7;
            const __half* src;
            if (TERMS == 3) {
                if (!isB) src = ((ch < 4) ? Abh : Abl) + (size_t)(m0 + row) * lda + kk + (ch & 3) * 8;
                else      src = ((ch < 4) ? Bbh : Bbl) + (size_t)(n0 + row) * ldb + kk + (ch & 3) * 8;
            } else {
                if (!isB) src = Abh + (size_t)(m0 + row) * lda + kk + ch * 8;
                else      src = Bbh + (size_t)(n0 + row) * ldb + kk + ch * 8;
            }
            uint32_t dst = base + st * STAGE_BYTES + isB * 16384
                         + row * 128 + ((ch ^ (row & 7)) << 4);
            cp_async16(dst, src);
        }
        cp_commit();
    };

    float acc[4][8][4];
#pragma unroll
    for (int i = 0; i < 4; ++i)
#pragma unroll
        for (int j = 0; j < 8; ++j)
#pragma unroll
            for (int r = 0; r < 4; ++r) acc[i][j][r] = 0.f;

#pragma unroll
    for (int s = 0; s < STAGES - 1; ++s) load_stage(s, s);

    const int rA   = wm + (lane & 15);
    const int selA = (lane >> 4);
    const int rB   = wn + ((lane >> 4) << 3) + (lane & 7);
    const int selB = (lane >> 3) & 1;

    for (int ks = 0; ks < NK; ++ks) {
        cp_wait<STAGES - 2>();   // own chunk-ks copies done
        __syncthreads();         // -> ALL threads' copies visible

        const uint32_t sA = base + (ks % STAGES) * STAGE_BYTES;
        const uint32_t sB = sA + 16384;

        // ---- first-kstep fragments BEFORE issuing next-stage cp.async ----
        uint32_t ah0[4][4], bh0[4][4];
        {
            const int cA = selA, cB = selB;     // kstep 0
#pragma unroll
            for (int mt = 0; mt < 4; ++mt) {
                int r = rA + mt * 16;
                ldsm_x4(ah0[mt], sA + r * 128 + ((cA ^ (r & 7)) << 4));
            }
#pragma unroll
            for (int ntp = 0; ntp < 4; ++ntp) {
                int r = rB + ntp * 16;
                ldsm_x4(bh0[ntp], sB + r * 128 + ((cB ^ (r & 7)) << 4));
            }
        }
        if (ks + STAGES - 1 < NK) load_stage(ks + STAGES - 1, (ks + STAGES - 1) % STAGES);
        else cp_commit();        // keep wait_group positional depth on tails

#pragma unroll
        for (int kstep = 0; kstep < KSTEPS; ++kstep) {
            const int cA = kstep * 2 + selA;
            const int cB = kstep * 2 + selB;
            uint32_t ah[4][4], bh[4][4];
            if (kstep == 0) {
#pragma unroll
                for (int mt = 0; mt < 4; ++mt)
#pragma unroll
                    for (int r4 = 0; r4 < 4; ++r4) ah[mt][r4] = ah0[mt][r4];
#pragma unroll
                for (int ntp = 0; ntp < 4; ++ntp)
#pragma unroll
                    for (int r4 = 0; r4 < 4; ++r4) bh[ntp][r4] = bh0[ntp][r4];
            } else {
#pragma unroll
                for (int mt = 0; mt < 4; ++mt) {
                    int r = rA + mt * 16;
                    ldsm_x4(ah[mt], sA + r * 128 + ((cA ^ (r & 7)) << 4));
                }
#pragma unroll
                for (int ntp = 0; ntp < 4; ++ntp) {
                    int r = rB + ntp * 16;
                    ldsm_x4(bh[ntp], sB + r * 128 + ((cB ^ (r & 7)) << 4));
                }
            }
            // term 1: ah * bh
#pragma unroll
            for (int mt = 0; mt < 4; ++mt)
#pragma unroll
                for (int nt = 0; nt < 8; ++nt)
                    mma16816(acc[mt][nt], ah[mt], &bh[nt >> 1][(nt & 1) * 2]);

            if (TERMS == 3) {
                // term 3: al * bh  — al loaded in 2-fragment halves
                {
                    uint32_t al[2][4];
#pragma unroll
                    for (int half = 0; half < 2; ++half) {
#pragma unroll
                        for (int m2 = 0; m2 < 2; ++m2) {
                            int mt = half * 2 + m2;
                            int r = rA + mt * 16;
                            ldsm_x4(al[m2], sA + r * 128 + (((cA + 4) ^ (r & 7)) << 4));
                        }
#pragma unroll
                        for (int m2 = 0; m2 < 2; ++m2)
#pragma unroll
                            for (int nt = 0; nt < 8; ++nt)
                                mma16816(acc[half * 2 + m2][nt], al[m2],
                                         &bh[nt >> 1][(nt & 1) * 2]);
                    }
                }
                // term 2: ah * bl  — bl loaded in 2-fragment halves
                {
                    uint32_t bl[2][4];
#pragma unroll
                    for (int half = 0; half < 2; ++half) {
#pragma unroll
                        for (int n2 = 0; n2 < 2; ++n2) {
                            int ntp = half * 2 + n2;
                            int r = rB + ntp * 16;
                            ldsm_x4(bl[n2], sB + r * 128 + (((cB + 4) ^ (r & 7)) << 4));
                        }
#pragma unroll
                        for (int mt = 0; mt < 4; ++mt)
#pragma unroll
                            for (int nt = 0; nt < 4; ++nt)
                                mma16816(acc[mt][half * 4 + nt], ah[mt],
                                         &bl[nt >> 1][(nt & 1) * 2]);
                    }
                }
            }
        }
    }

    // ---- epilogue ----
    const int erow = lane >> 2;
    const int ecol = (lane & 3) * 2;

    float bv[8][2];
    if (MODE == 0 || MODE == 3) {
#pragma unroll
        for (int nt = 0; nt < 8; ++nt) {
            bv[nt][0] = bias[n0 + wn + nt * 8 + ecol];
            bv[nt][1] = bias[n0 + wn + nt * 8 + ecol + 1];
        }
    }

#pragma unroll
    for (int mt = 0; mt < 4; ++mt) {
#pragma unroll
        for (int nt = 0; nt < 8; ++nt) {
            int m1 = m0 + wm + mt * 16 + erow;
            int nn = n0 + wn + nt * 8 + ecol;
            size_t off1 = ((size_t)b * HWN + m1) * (size_t)Nfull + nn;
            size_t off2 = off1 + 8 * (size_t)Nfull;
            if (MODE == 0) {
                float y0 = acc[mt][nt][0] + bv[nt][0];
                float y1 = acc[mt][nt][1] + bv[nt][1];
                float y2 = acc[mt][nt][2] + bv[nt][0];
                float y3 = acc[mt][nt][3] + bv[nt][1];
                __half h0, l0, h1, l1, h2, l2, h3, l3;
                split_f32(y0, h0, l0); split_f32(y1, h1, l1);
                split_f32(y2, h2, l2); split_f32(y3, h3, l3);
                *(__half2*)(Ch + off1) = __halves2half2(h0, h1);
                *(__half2*)(Cl + off1) = __halves2half2(l0, l1);
                *(__half2*)(Ch + off2) = __halves2half2(h2, h3);
                *(__half2*)(Cl + off2) = __halves2half2(l2, l3);
            } else if (MODE == 3) {
                float y0 = acc[mt][nt][0] + bv[nt][0];
                float y1 = acc[mt][nt][1] + bv[nt][1];
                float y2 = acc[mt][nt][2] + bv[nt][0];
                float y3 = acc[mt][nt][3] + bv[nt][1];
                *(__half2*)(Ch + off1) = __halves2half2(__float2half(y0), __float2half(y1));
                *(__half2*)(Ch + off2) = __halves2half2(__float2half(y2), __float2half(y3));
            } else {
                float2 r1 = make_float2(acc[mt][nt][0], acc[mt][nt][1]);
                float2 r2 = make_float2(acc[mt][nt][2], acc[mt][nt][3]);
                if (MODE == 2) {
                    float2 x1 = *(const float2*)(xadd + off1);
                    float2 x2 = *(const float2*)(xadd + off2);
                    r1.x += x1.x; r1.y += x1.y;
                    r2.x += x2.x; r2.y += x2.y;
                }
                *(float2*)(Cf + off1) = r1;
                *(float2*)(Cf + off2) = r2;
            }
        }
    }
}

// ============================================================================
// softmax: one WARP per row (1024 cols = 8 float4 per lane), shfl-only
// ============================================================================
__global__ void __launch_bounds__(256)
softmax_h(const float* __restrict__ logits, __half2* __restrict__ ah)
{
    const int lane = threadIdx.x & 31;
    const int w    = threadIdx.x >> 5;
    const size_t row = (size_t)blockIdx.x * 8 + w;

    const float4* src = (const float4*)(logits + row * HWN);
    float4 v[8];
#pragma unroll
    for (int i = 0; i < 8; ++i) v[i] = src[lane + 32 * i];

    float m = -3.4e38f;
#pragma unroll
    for (int i = 0; i < 8; ++i)
        m = fmaxf(m, fmaxf(fmaxf(v[i].x, v[i].y), fmaxf(v[i].z, v[i].w)));
#pragma unroll
    for (int o = 16; o; o >>= 1) m = fmaxf(m, __shfl_xor_sync(0xffffffffu, m, o));

    float s = 0.f;
#pragma unroll
    for (int i = 0; i < 8; ++i) {
        v[i].x = __expf(v[i].x - m); v[i].y = __expf(v[i].y - m);
        v[i].z = __expf(v[i].z - m); v[i].w = __expf(v[i].w - m);
        s += (v[i].x + v[i].y) + (v[i].z + v[i].w);
    }
#pragma unroll
    for (int o = 16; o; o >>= 1) s += __shfl_xor_sync(0xffffffffu, s, o);

    const float inv = 1.f / s;
    __half2* dst = ah + row * (HWN / 2);
#pragma unroll
    for (int i = 0; i < 8; ++i) {
        int c4 = lane + 32 * i;
        dst[c4 * 2]     = __halves2half2(__float2half(v[i].x * inv),
                                         __float2half(v[i].y * inv));
        dst[c4 * 2 + 1] = __halves2half2(__float2half(v[i].z * inv),
                                         __float2half(v[i].w * inv));
    }
}

// ============================================================================
// Launch (R15 topology: v-proj on s2 back-filling the qk->logits chain)
// ============================================================================
extern "C" void kernel_launch(void* const* d_in, const int* in_sizes, int n_in,
                              void* d_out, int out_size)
{
    (void)in_sizes; (void)n_in; (void)out_size;
    const float* x  = (const float*)d_in[0];
    const float* Wq = (const float*)d_in[1];
    const float* bq = (const float*)d_in[2];
    const float* Wk = (const float*)d_in[3];
    const float* bk = (const float*)d_in[4];
    const float* Wv = (const float*)d_in[5];
    const float* bv = (const float*)d_in[6];
    float* out = (float*)d_out;

    __half *xth, *xtl, *wqkh, *wqkl, *wvh, *qkh, *qkl, *vh, *aah;
    float *lg, *bqk;
    cudaGetSymbolAddress((void**)&xth,  g_xt_h);
    cudaGetSymbolAddress((void**)&xtl,  g_xt_l);
    cudaGetSymbolAddress((void**)&wqkh, g_wqk_h);
    cudaGetSymbolAddress((void**)&wqkl, g_wqk_l);
    cudaGetSymbolAddress((void**)&bqk,  g_bqk);
    cudaGetSymbolAddress((void**)&wvh,  g_wv_h);
    cudaGetSymbolAddress((void**)&qkh,  g_qk_h);
    cudaGetSymbolAddress((void**)&qkl,  g_qk_l);
    cudaGetSymbolAddress((void**)&vh,   g_v_h);
    cudaGetSymbolAddress((void**)&lg,   g_logits);
    cudaGetSymbolAddress((void**)&aah,  g_a_h);

    cudaFuncSetAttribute(mma_gemm<1024, 3, 0>, cudaFuncAttributeMaxDynamicSharedMemorySize, SMEM_TOTAL);
    cudaFuncSetAttribute(mma_gemm<512,  3, 1>, cudaFuncAttributeMaxDynamicSharedMemorySize, SMEM_TOTAL);
    cudaFuncSetAttribute(mma_gemm<1024, 1, 3>, cudaFuncAttributeMaxDynamicSharedMemorySize, SMEM_TOTAL);
    cudaFuncSetAttribute(mma_gemm<1024, 1, 2>, cudaFuncAttributeMaxDynamicSharedMemorySize, SMEM_TOTAL);

    static cudaStream_t s2 = nullptr;
    static cudaEvent_t ev_x = nullptr, ev_w = nullptr, ev_join = nullptr;
    if (s2 == nullptr) {
        cudaStreamCreateWithFlags(&s2, cudaStreamNonBlocking);
        cudaEventCreateWithFlags(&ev_x,    cudaEventDisableTiming);
        cudaEventCreateWithFlags(&ev_w,    cudaEventDisableTiming);
        cudaEventCreateWithFlags(&ev_join, cudaEventDisableTiming);
    }

    // fork s2 from the main stream before any s2 work
    cudaEventRecord(ev_x, 0);
    cudaStreamWaitEvent(s2, ev_x, 0);

    // conversions: transpose on main, weight pack on s2 (independent)
    transpose_split_x<<<dim3(32, 32, 32), 512>>>(x, xth, xtl);
    pack_weights<<<4096, 256, 0, s2>>>(Wq, Wk, Wv, bq, bk, wqkh, wqkl, wvh, bqk);
    cudaEventRecord(ev_w, s2);           // weights ready
    cudaEventRecord(ev_x, 0);            // xt ready
    cudaStreamWaitEvent(0, ev_w, 0);     // main needs wqk for qk-proj
    cudaStreamWaitEvent(s2, ev_x, 0);    // s2 needs xt for v-proj

    // qk-proj first (critical path), then v-proj back-fills on s2
    mma_gemm<1024, 3, 0><<<dim3(1024 / BN, HWN / BM, BB), 128, SMEM_TOTAL>>>(
        xth, xtl, wqkh, wqkl, CC, CC, (size_t)HWN * CC, 0,
        bqk, nullptr, nullptr, qkh, qkl, 1024);
    mma_gemm<1024, 1, 3><<<dim3(CC / BN, HWN / BM, BB), 128, SMEM_TOTAL, s2>>>(
        xth, nullptr, wvh, nullptr, CC, CC, (size_t)HWN * CC, 0,
        bv, nullptr, nullptr, vh, nullptr, CC);
    cudaEventRecord(ev_join, s2);

    // logits[b][n][m] = q_n . k_m  (K=512, 3-term) — q/k are column slices of qk
    mma_gemm<512, 3, 1><<<dim3(HWN / BN, HWN / BM, BB), 128, SMEM_TOTAL>>>(
        qkh, qkl, qkh + CH, qkl + CH, 1024, 1024,
        (size_t)HWN * 1024, (size_t)HWN * 1024,
        nullptr, nullptr, lg, nullptr, nullptr, HWN);

    // softmax -> fp16 attention (warp-per-row)
    softmax_h<<<BB * HWN / 8, 256>>>(lg, (__half2*)aah);

    // join: out-GEMM needs v (s2) and attn (main)
    cudaStreamWaitEvent(0, ev_join, 0);

    // out[b][i][j] = v . attn + x  (K=1024, fp16)
    mma_gemm<1024, 1, 2><<<dim3(HWN / BN, HWN / BM, BB), 128, SMEM_TOTAL>>>(
        vh, nullptr, aah, nullptr, CC, HWN, (size_t)HWN * CC, (size_t)HWN * HWN,
        nullptr, x, out, nullptr, nullptr, HWN);
}